// round 6
// baseline (speedup 1.0000x reference)
#include <cuda_runtime.h>
#include <math.h>
#include <stdint.h>

// ---------------- problem constants ----------------
#define BB   128
#define TT   1024
#define II   256
#define HH   512
#define OO   256
#define LOUT 64
#define NCTA 128          // 16 clusters x 8 CTAs

#define WOP  516          // W_out smem row stride (floats)
#define XS   130          // xproj smem row stride

#define XPROJ_SMEM (2 * 64 * XS * 4)
// k_rnn smem floats: hb 8192, part 4096, wouts 32*WOP=16512, sbhh 512, sbih 512,
// sbout 256 -> 30080; mbar[8] u64 at float-offset 30080 (byte 120320, 8B aligned)
#define MB_OFF     30080
#define RNN_FLOATS (MB_OFF + 32)
#define RNN_SMEM   (RNN_FLOATS * 4)          // 120448 B

__device__ float g_xproj[(size_t)BB * TT * HH];   // 256 MB scratch

union U64 { unsigned long long u; float2 f; };

__device__ __forceinline__ void ffma2(U64 &d, unsigned long long a, U64 b) {
    asm("fma.rn.f32x2 %0, %1, %2, %0;" : "+l"(d.u) : "l"(a), "l"(b.u));
}

__device__ __forceinline__ uint32_t smem_u32(const void* p) {
    return (uint32_t)__cvta_generic_to_shared(p);
}

#define CLUSTER_SYNC() do { \
    asm volatile("barrier.cluster.arrive.aligned;" ::: "memory"); \
    asm volatile("barrier.cluster.wait.aligned;"   ::: "memory"); \
} while (0)

// mbarrier wait (parity, acquire at cluster scope). Warp-uniform call sites.
__device__ __forceinline__ void mbar_wait_cluster(uint32_t addr, uint32_t parity) {
    uint32_t done;
    asm volatile(
        "{\n\t.reg .pred p;\n\t"
        "mbarrier.try_wait.parity.acquire.cluster.shared::cta.b64 p, [%1], %2;\n\t"
        "selp.b32 %0, 1, 0, p;\n\t}"
        : "=r"(done) : "r"(addr), "r"(parity) : "memory");
    if (!done) {
        asm volatile(
            "{\n\t"
            ".reg .pred P1;\n\t"
            "WL_%=:\n\t"
            "mbarrier.try_wait.parity.acquire.cluster.shared::cta.b64 P1, [%0], %1, 0x989680;\n\t"
            "@P1 bra.uni WD_%=;\n\t"
            "bra.uni WL_%=;\n\t"
            "WD_%=:\n\t"
            "}"
            :: "r"(addr), "r"(parity) : "memory");
    }
}

// ============================================================================
// Kernel 1: x_proj = x @ W_ih^T + b_ih  (unchanged; proven)
// ============================================================================
__global__ void __launch_bounds__(256, 2)
k_xproj(const float* __restrict__ x, const int* __restrict__ lengths,
        const float* __restrict__ W_ih, const float* __restrict__ b_ih)
{
    extern __shared__ float sm[];
    float* xs = sm;
    float* ws = sm + 64 * XS;

    const int b  = blockIdx.z;
    const int t0 = blockIdx.y * 64;
    const int h0 = blockIdx.x * 64;
    if (t0 >= lengths[b]) return;

    const int tid = threadIdx.x;
    const int tr  = tid >> 4;
    const int tc  = tid & 15;

    U64 acc[4][4];
    #pragma unroll
    for (int i = 0; i < 4; i++)
        #pragma unroll
        for (int j = 0; j < 4; j++) acc[i][j].u = 0ULL;

    for (int kc = 0; kc < 2; kc++) {
        __syncthreads();
        #pragma unroll
        for (int i = 0; i < 16; i++) {
            int e = tid + 256 * i;
            int r = e >> 6, cc = e & 63;
            float2 xv = *(const float2*)(x + ((size_t)b * TT + t0 + r) * II + kc * 128 + 2 * cc);
            *(float2*)(xs + r * XS + 2 * cc) = xv;
            float2 wv = *(const float2*)(W_ih + (size_t)(h0 + r) * II + kc * 128 + 2 * cc);
            *(float2*)(ws + r * XS + 2 * cc) = wv;
        }
        __syncthreads();
        #pragma unroll 4
        for (int kp = 0; kp < 64; kp++) {
            U64 xf[4], wf[4];
            #pragma unroll
            for (int i = 0; i < 4; i++) xf[i].f = *(const float2*)(xs + (tr + 16*i) * XS + 2 * kp);
            #pragma unroll
            for (int j = 0; j < 4; j++) wf[j].f = *(const float2*)(ws + (tc + 16*j) * XS + 2 * kp);
            #pragma unroll
            for (int i = 0; i < 4; i++)
                #pragma unroll
                for (int j = 0; j < 4; j++) ffma2(acc[i][j], xf[i].u, wf[j]);
        }
    }

    #pragma unroll
    for (int i = 0; i < 4; i++)
        #pragma unroll
        for (int j = 0; j < 4; j++) {
            int t = t0 + tr + 16 * i;
            int h = h0 + tc + 16 * j;
            g_xproj[((size_t)b * TT + t) * HH + h] = acc[i][j].f.x + acc[i][j].f.y + b_ih[h];
        }
}

// ============================================================================
// Kernel 2: clustered persistent RNN; per-source mbarrier handshake in the
// encoder (chunk kq comes solely from cluster rank kq -> thread waits one
// mbar), CLUSTER_SYNC in the short decoder. W_hh in regs, broadcast LDS GEMM,
// distributed DSMEM pushes, per-row frozen parity, xp prefetched 1 step ahead.
// ============================================================================
__global__ void __launch_bounds__(512, 1) __cluster_dims__(8, 1, 1)
k_rnn(const int* __restrict__ lengths, const float* __restrict__ W_hh,
      const float* __restrict__ b_hh, const float* __restrict__ b_ih,
      const float* __restrict__ W_out, const float* __restrict__ b_out,
      float* __restrict__ out)
{
    extern __shared__ float sm[];
    float* hb    = sm;                 // [2][8][512] double-buffered replicated h
    float* part  = sm + 8192;          // [8][512] k-split partials
    float* wouts = part + 4096;        // [32][WOP]
    float* sbhh  = wouts + 32 * WOP;   // [512]
    float* sbih  = sbhh + 512;         // [512]
    float* sbout = sbih + 512;         // [256]

    const int tid    = threadIdx.x;
    const int cta    = blockIdx.x;
    const int rg     = cta >> 3;
    const int cg     = cta & 7;
    const int c      = tid & 63;
    const int kq     = tid >> 6;       // 0..7: consumed k-chunk AND owned output row
    const int b_base = rg * 8;
    const int col_c  = cg * 64 + c;

    // DSMEM peer bases for hb, local/remote mbar addresses
    uint32_t peer[8];
    {
        uint32_t hbase = smem_u32(hb);
        #pragma unroll
        for (int rk = 0; rk < 8; rk++)
            asm("mapa.shared::cluster.u32 %0, %1, %2;" : "=r"(peer[rk]) : "r"(hbase), "r"(rk));
    }
    const uint32_t mbar_base = smem_u32(sm + MB_OFF);
    const uint32_t wait_addr = mbar_base + kq * 8;   // local mbar for my source chunk
    uint32_t arr_addr = 0;
    if (tid < 8) {                                   // thread rk arrives at rank rk's mbar[cg]
        uint32_t rb;
        asm("mapa.shared::cluster.u32 %0, %1, %2;" : "=r"(rb) : "r"(mbar_base), "r"(tid));
        arr_addr = rb + (uint32_t)cg * 8;
    }
    if (tid == 0) {
        #pragma unroll
        for (int i = 0; i < 8; i++)
            asm volatile("mbarrier.init.shared.b64 [%0], %1;"
                         :: "r"(mbar_base + i * 8), "r"(1u) : "memory");
    }

    // W_hh[col_c][kq*64 .. +64] -> 32 U64 regs (permanent)
    U64 W[32];
    {
        const U64* wsrc = (const U64*)(W_hh + (size_t)col_c * HH + kq * 64);
        #pragma unroll
        for (int j = 0; j < 32; j++) W[j] = wsrc[j];
    }

    // stage biases + W_out slice; zero hb[0]
    sbhh[tid] = b_hh[tid]; sbih[tid] = b_ih[tid];
    if (tid < 256) sbout[tid] = b_out[tid];
    #pragma unroll
    for (int i = 0; i < 16; i++) {
        int e = tid + 512 * i;
        int r = e >> 8, cc = e & 255;
        float2 v = *(const float2*)(W_out + (size_t)(cg * 32 + r) * HH + 2 * cc);
        *(float2*)(wouts + r * WOP + 2 * cc) = v;
    }
    #pragma unroll
    for (int i = 0; i < 8; i++) hb[tid + 512 * i] = 0.f;   // hb[0] = 0

    int L[8];
    int tmax = 0;
    #pragma unroll
    for (int r = 0; r < 8; r++) { L[r] = lengths[b_base + r]; tmax = max(tmax, L[r]); }
    const int L_own = L[kq];
    const float* xp_base = g_xproj + ((size_t)(b_base + kq) * TT) * HH + col_c;

    __syncthreads();
    const float bhh_c = sbhh[col_c];
    const float bih_c = sbih[col_c];
    CLUSTER_SYNC();        // mbar init + hb[0] visible cluster-wide before any push

    // =================== encoder (to this cluster's tmax) =====================
    uint32_t ph = 0;
    float xp_next = (0 < L_own) ? xp_base[0] : 0.f;

    for (int t = 0; t < tmax; t++) {
        const int rp = t & 1, wp = rp ^ 1;

        const float xp = xp_next;
        if (t + 1 < L_own) xp_next = xp_base[(size_t)(t + 1) * HH];   // hide DRAM 1 step

        if (t) { mbar_wait_cluster(wait_addr, ph); ph ^= 1; }         // my chunk arrived

        // GEMM: partial over k-chunk kq for each active row
        #pragma unroll
        for (int r = 0; r < 8; r++) {
            if (t < L[r]) {
                const ulonglong2* h2 = (const ulonglong2*)(hb + rp * 4096 + r * 512 + kq * 64);
                U64 a0, a1; a0.u = 0ULL; a1.u = 0ULL;
                #pragma unroll
                for (int j = 0; j < 16; j++) {
                    ulonglong2 q = h2[j];
                    ffma2(a0, q.x, W[2 * j]);
                    ffma2(a1, q.y, W[2 * j + 1]);
                }
                part[kq * 512 + r * 64 + c] = (a0.f.x + a1.f.x) + (a0.f.y + a1.f.y);
            }
        }
        __syncthreads();

        // reduce + tanh + push (thread owns output row kq, col c)
        if (t < L_own) {
            float s = bhh_c + xp;
            #pragma unroll
            for (int k = 0; k < 8; k++) s += part[k * 512 + kq * 64 + c];
            float v = tanhf(s);
            uint32_t off = (uint32_t)(wp * 4096 + kq * 512 + col_c) * 4u;
            #pragma unroll
            for (int rk = 0; rk < 8; rk++)
                asm volatile("st.shared::cluster.f32 [%0], %1;"
                             :: "r"(peer[rk] + off), "f"(v) : "memory");
        }
        __syncthreads();   // all pushes issued CTA-wide

        if (tid < 8) {     // publish: cumulative cluster fence, then 1 arrive per dest
            asm volatile("fence.acq_rel.cluster;" ::: "memory");
            asm volatile("mbarrier.arrive.shared::cluster.b64 _, [%0];"
                         :: "r"(arr_addr) : "memory");
        }
    }

    CLUSTER_SYNC();        // final pushes visible everywhere; clusters aligned
    // normalize: rows whose final value is in buffer 1 -> buffer 0 (local copy)
    #pragma unroll
    for (int r = 0; r < 8; r++)
        if (L[r] & 1) hb[r * 512 + tid] = hb[4096 + r * 512 + tid];
    __syncthreads();
    CLUSTER_SYNC();        // no decoder push may land before normalize completes

    // =================== decoder (64 steps, CLUSTER_SYNC protocol) ============
    for (int s = 0; s < LOUT; s++) {
        const int rp = s & 1, wp = rp ^ 1;

        #pragma unroll
        for (int r = 0; r < 8; r++) {
            const ulonglong2* h2 = (const ulonglong2*)(hb + rp * 4096 + r * 512 + kq * 64);
            U64 a0, a1; a0.u = 0ULL; a1.u = 0ULL;
            #pragma unroll
            for (int j = 0; j < 16; j++) {
                ulonglong2 q = h2[j];
                ffma2(a0, q.x, W[2 * j]);
                ffma2(a1, q.y, W[2 * j + 1]);
            }
            part[kq * 512 + r * 64 + c] = (a0.f.x + a1.f.x) + (a0.f.y + a1.f.y);
        }
        __syncthreads();

        {
            float sv = bih_c + bhh_c;
            #pragma unroll
            for (int k = 0; k < 8; k++) sv += part[k * 512 + kq * 64 + c];
            float v = tanhf(sv);
            uint32_t off = (uint32_t)(wp * 4096 + kq * 512 + col_c) * 4u;
            #pragma unroll
            for (int rk = 0; rk < 8; rk++)
                asm volatile("st.shared::cluster.f32 [%0], %1;"
                             :: "r"(peer[rk] + off), "f"(v) : "memory");
        }

        CLUSTER_SYNC();    // new h (parity wp) complete in every replica

        // out[b, s, cg*32+oo] from new h; 256 threads, K=512
        if (tid < 256) {
            const int rr = tid >> 5;
            const int oo = tid & 31;
            const ulonglong2* h2 = (const ulonglong2*)(hb + wp * 4096 + rr * 512);
            const ulonglong2* w2 = (const ulonglong2*)(wouts + oo * WOP);
            U64 a0, a1; a0.u = 0ULL; a1.u = 0ULL;
            #pragma unroll 8
            for (int j = 0; j < 128; j++) {
                ulonglong2 qh = h2[j];
                ulonglong2 qw = w2[j];
                U64 wb0, wb1; wb0.u = qw.x; wb1.u = qw.y;
                ffma2(a0, qh.x, wb0);
                ffma2(a1, qh.y, wb1);
            }
            float val = (a0.f.x + a1.f.x) + (a0.f.y + a1.f.y) + sbout[cg * 32 + oo];
            out[((size_t)(b_base + rr) * LOUT + s) * OO + cg * 32 + oo] = val;
        }
        // safe: step s+1 pushes target parity rp (!= wp read here) and are gated
        // by the next CLUSTER_SYNC, which needs all threads' arrival.
    }

    CLUSTER_SYNC();   // keep cluster alive until all DSMEM traffic quiesces
}

// ---------------- launch ----------------
extern "C" void kernel_launch(void* const* d_in, const int* in_sizes, int n_in,
                              void* d_out, int out_size)
{
    int k = 0;
    const float* x       = (const float*)d_in[k++];
    const int*   lengths = (const int*)  d_in[k++];
    if (k < n_in && in_sizes[k] == 1) k++;           // out_lengths scalar (if present)
    const float* W_ih    = (const float*)d_in[k++];
    const float* b_ih    = (const float*)d_in[k++];
    const float* W_hh    = (const float*)d_in[k++];
    const float* b_hh    = (const float*)d_in[k++];
    const float* W_out   = (const float*)d_in[k++];
    const float* b_out   = (const float*)d_in[k++];
    float* out = (float*)d_out;

    cudaFuncSetAttribute(k_xproj, cudaFuncAttributeMaxDynamicSharedMemorySize, XPROJ_SMEM);
    cudaFuncSetAttribute(k_rnn,   cudaFuncAttributeMaxDynamicSharedMemorySize, RNN_SMEM);

    dim3 g1(HH / 64, TT / 64, BB);
    k_xproj<<<g1, 256, XPROJ_SMEM>>>(x, lengths, W_ih, b_ih);
    k_rnn<<<NCTA, 512, RNN_SMEM>>>(lengths, W_hh, b_hh, b_ih, W_out, b_out, out);
}